// round 13
// baseline (speedup 1.0000x reference)
#include <cuda_runtime.h>
#include <cuda_bf16.h>
#include <cstdint>

// SimplePatchScorer: x (512,3,224,224) f32, W (1,768) f32, b (1,) f32
// out (512,196) f32.
//
// f = t*588 + e; t = i*16 + j; e = band*14 + wn; 42 bands of 3584 floats
// (16 image rows x 224 cols), band float4 g = i*56 + wn*4 + jp.
// row = f/768, k = f mod 768. Per t: kappa = 588t mod 768, T = 588t/768;
// a = kappa + e crosses 768 at most once -> l accum (row T) / h (row T+1).
//
// R13: RF was the in-flight-bytes window (R7/R11/R12 law). Stage x through
// SMEM with cp.async.bulk (UBLKCP), 3-band pipeline: in-flight bytes now
// SMEM-resident, one bulk op per 14336B band (perfect row locality, no LSU
// per-element issue, no branch-limited batching). Compute = conflict-free
// LDS + the R7-proven predicated dual-accumulator FMA.

#define BATCH     512
#define NROWS     196
#define KLEN      768
#define NBANDS    42
#define BAND_F4   896
#define BAND_BYTES 14336
#define IMG_ELEMS 150528
#define NST       3
#define SWSZ      792            // 768 + 768/32 swizzle pad
#define TPB       256

__device__ __forceinline__ uint32_t smem_u32(const void* p) {
    uint32_t a;
    asm("{ .reg .u64 t; cvta.to.shared.u64 t, %1; cvt.u32.u64 %0, t; }"
        : "=r"(a) : "l"(p));
    return a;
}

__global__ __launch_bounds__(TPB, 4)
void patch_scorer_kernel(const float* __restrict__ x,
                         const float* __restrict__ W,
                         const float* __restrict__ bias,
                         float* __restrict__ out)
{
    __shared__ __align__(16) float4 stg[NST][BAND_F4];   // 43008 B
    __shared__ float sW[SWSZ];                           //  3168 B
    __shared__ float sAcc[200];                          //   800 B
    __shared__ __align__(8) unsigned long long mbar[NST];

    const int tid = threadIdx.x;
    const int b   = blockIdx.x;

    for (int k = tid; k < KLEN; k += TPB)
        sW[k + (k >> 5)] = W[k];
    if (tid < 200) sAcc[tid] = 0.0f;
    if (tid < NST) {
        const uint32_t mb = smem_u32(&mbar[tid]);
        asm volatile("mbarrier.init.shared.b64 [%0], %1;"
                     :: "r"(mb), "r"(1) : "memory");
    }
    __syncthreads();

    const char* src = (const char*)(x + (size_t)b * IMG_ELEMS);

    // prologue: issue bands 0..2 into stages 0..2
    if (tid == 0) {
        #pragma unroll
        for (int s = 0; s < NST; ++s) {
            const uint32_t mb  = smem_u32(&mbar[s]);
            const uint32_t dst = smem_u32(&stg[s][0]);
            asm volatile("mbarrier.arrive.expect_tx.shared.b64 _, [%0], %1;"
                         :: "r"(mb), "r"(BAND_BYTES) : "memory");
            asm volatile(
                "cp.async.bulk.shared::cluster.global.mbarrier::complete_tx::bytes "
                "[%0], [%1], %2, [%3];"
                :: "r"(dst), "l"(src + (size_t)s * BAND_BYTES),
                   "r"(BAND_BYTES), "r"(mb) : "memory");
        }
    }

    // thread = (v wn-group, i patch row, jp float4 col group)
    const int v  = tid >> 6;         // wn in {v, v+4, v+8, (v+12 if v<2)}
    const int i  = (tid >> 2) & 15;
    const int jp = tid & 3;
    const int gb = i * 56 + jp;      // float4 base within band

    // per sub-element m (t_m = i*16 + 4jp + m): kappa, T
    const int tb = i * 16 + jp * 4;
    const int T0 = (tb * 588) / KLEN,       K0 = tb * 588 - T0 * KLEN;
    const int T1 = ((tb + 1) * 588) / KLEN, K1 = (tb + 1) * 588 - T1 * KLEN;
    const int T2 = ((tb + 2) * 588) / KLEN, K2 = (tb + 2) * 588 - T2 * KLEN;
    const int T3 = ((tb + 3) * 588) / KLEN, K3 = (tb + 3) * 588 - T3 * KLEN;

    float l0 = 0.f, h0 = 0.f, l1 = 0.f, h1 = 0.f;
    float l2 = 0.f, h2 = 0.f, l3 = 0.f, h3 = 0.f;

    int s = 0, ph = 0, bb = 0;       // stage, parity, 14*band
    for (int band = 0; band < NBANDS; ++band) {
        {   // wait for this band's copy
            const uint32_t mb = smem_u32(&mbar[s]);
            uint32_t ok = 0;
            do {
                asm volatile(
                    "{ .reg .pred p;\n\t"
                    "mbarrier.try_wait.parity.shared::cta.b64 p, [%1], %2;\n\t"
                    "selp.b32 %0, 1, 0, p; }"
                    : "=r"(ok) : "r"(mb), "r"(ph) : "memory");
            } while (!ok);
        }

        const float4* buf = &stg[s][0];
        #pragma unroll
        for (int u = 0; u < 4; ++u) {
            const int wn = v + 4 * u;
            if (wn < 14) {                       // warp-uniform branch
                const float4 vx = buf[gb + wn * 4];
                const int e = bb + wn;

                int a = K0 + e; bool pr = a < KLEN;
                int aw = pr ? a : a - KLEN; float w = sW[aw + (aw >> 5)];
                if (pr) l0 += vx.x * w; else h0 += vx.x * w;

                a = K1 + e; pr = a < KLEN;
                aw = pr ? a : a - KLEN; w = sW[aw + (aw >> 5)];
                if (pr) l1 += vx.y * w; else h1 += vx.y * w;

                a = K2 + e; pr = a < KLEN;
                aw = pr ? a : a - KLEN; w = sW[aw + (aw >> 5)];
                if (pr) l2 += vx.z * w; else h2 += vx.z * w;

                a = K3 + e; pr = a < KLEN;
                aw = pr ? a : a - KLEN; w = sW[aw + (aw >> 5)];
                if (pr) l3 += vx.w * w; else h3 += vx.w * w;
            }
        }

        __syncthreads();                         // stage s fully consumed

        const int nb = band + NST;
        if (tid == 0 && nb < NBANDS) {           // refill stage s
            const uint32_t mb  = smem_u32(&mbar[s]);
            const uint32_t dst = smem_u32(&stg[s][0]);
            asm volatile("mbarrier.arrive.expect_tx.shared.b64 _, [%0], %1;"
                         :: "r"(mb), "r"(BAND_BYTES) : "memory");
            asm volatile(
                "cp.async.bulk.shared::cluster.global.mbarrier::complete_tx::bytes "
                "[%0], [%1], %2, [%3];"
                :: "r"(dst), "l"(src + (size_t)nb * BAND_BYTES),
                   "r"(BAND_BYTES), "r"(mb) : "memory");
        }

        bb += 14;
        if (++s == NST) { s = 0; ph ^= 1; }
    }

    atomicAdd(&sAcc[T0    ], l0);
    atomicAdd(&sAcc[T0 + 1], h0);
    atomicAdd(&sAcc[T1    ], l1);
    atomicAdd(&sAcc[T1 + 1], h1);
    atomicAdd(&sAcc[T2    ], l2);
    atomicAdd(&sAcc[T2 + 1], h2);
    atomicAdd(&sAcc[T3    ], l3);
    atomicAdd(&sAcc[T3 + 1], h3);

    __syncthreads();

    if (tid < NROWS)
        out[(size_t)b * NROWS + tid] = sAcc[tid] + bias[0];
}

extern "C" void kernel_launch(void* const* d_in, const int* in_sizes, int n_in,
                              void* d_out, int out_size)
{
    const float* x  = (const float*)d_in[0];   // (512,3,224,224)
    const float* W  = (const float*)d_in[1];   // (1,768)
    const float* bv = (const float*)d_in[2];   // (1,)
    float* out = (float*)d_out;                // (512,196)

    patch_scorer_kernel<<<BATCH, TPB>>>(x, W, bv, out);
}

// round 14
// speedup vs baseline: 1.5311x; 1.5311x over previous
#include <cuda_runtime.h>
#include <cuda_bf16.h>

// SimplePatchScorer: x (512,3,224,224) f32, W (1,768) f32, b (1,) f32
// out (512,196) f32.
//
// f = t*588 + e; t = i*16 + j; e = band*14 + wn (42 bands of 896 float4).
// row = f/768, k = f mod 768.
//
// R14 (base = R7, 55.8us; loop identical): fix WAVE IMBALANCE.
// 512 CTAs over 148 SMs -> 68 SMs run 4 CTAs, 80 run 3: wall set by the
// 4-CTA SMs (~16% waste). Split each image into two CTAs along i using
// 128*588 = 98*768: t in [0,128) ends EXACTLY at an output-row boundary,
// so CTA (b, ihalf) owns rows ihalf*98..+97 exclusively - no combine.
// grid = 1024 x 128 thr (same 4096 warps, same per-thread work as R7);
// max 7 vs avg 6.92 CTAs/SM -> ~1% imbalance. launch_bounds(128,7) keeps
// the 73-reg budget so LDG batching isn't squeezed (R11 lesson).

#define BATCH    512
#define NROWS    196
#define KLEN     768
#define IMG_F4   37632           // 3*224*224/4
#define SW2SZ    1584            // 1536 + 1536/32
#define TPB      128

__global__ __launch_bounds__(TPB, 7)
void patch_scorer_kernel(const float* __restrict__ x,
                         const float* __restrict__ W,
                         const float* __restrict__ bias,
                         float* __restrict__ out)
{
    __shared__ float sW2s[SW2SZ];    // sW2s[a + (a>>5)] = W[a % 768], a<1536
    __shared__ float sAcc[100];      // 98 local rows + pad for zero hi-adds

    const int tid   = threadIdx.x;
    const int b     = blockIdx.x >> 1;   // image
    const int ihalf = blockIdx.x & 1;    // patch-row half: i in [8*ihalf, +8)

    #pragma unroll
    for (int a = tid; a < 2 * KLEN; a += TPB) {
        const int k = (a < KLEN) ? a : a - KLEN;
        sW2s[a + (a >> 5)] = W[k];
    }
    if (tid < 100) sAcc[tid] = 0.0f;
    __syncthreads();

    const int q  = tid >> 5;         // e-quarter 0..3 (warp id)
    const int il = (tid >> 2) & 7;   // local patch row 0..7
    const int jp = tid & 3;          // float4 group (j = 4jp..4jp+3)

    // local t (t_local = t - 128*ihalf): rows/weights use t_local since
    // 128*588 = 98*768 makes the half self-contained.
    const int tb = il * 16 + jp * 4; // t_local of element m=0
    const int e0 = q * 147;

    const int f0 = tb * 588 + e0;    // local f of element m=0
    const int R0 = f0 / KLEN;        // local rows (0..97)
    const int R1 = (f0 +  588) / KLEN;
    const int R2 = (f0 + 1176) / KLEN;
    const int R3 = (f0 + 1764) / KLEN;
    int a0 = f0          - R0 * KLEN;
    int a1 = (f0 +  588) - R1 * KLEN;
    int a2 = (f0 + 1176) - R2 * KLEN;
    int a3 = (f0 + 1764) - R3 * KLEN;

    const int beta = e0 / 14;        // starting band
    int       wn   = e0 - beta * 14;

    const int i = ihalf * 8 + il;    // global patch row for addressing
    const float4* px = (const float4*)x + (size_t)b * IMG_F4 + i * 56 + jp;
    int off = beta * 896 + wn * 4;   // float4 offset within image

    float l0 = 0.f, h0 = 0.f, l1 = 0.f, h1 = 0.f;
    float l2 = 0.f, h2 = 0.f, l3 = 0.f, h3 = 0.f;

    #pragma unroll 7
    for (int n = 0; n < 147; ++n) {
        const float4 v = __ldcs(&px[off]);

        const float w0 = sW2s[a0 + (a0 >> 5)];
        const float w1 = sW2s[a1 + (a1 >> 5)];
        const float w2 = sW2s[a2 + (a2 >> 5)];
        const float w3 = sW2s[a3 + (a3 >> 5)];

        if (a0 < KLEN) l0 += v.x * w0; else h0 += v.x * w0;
        if (a1 < KLEN) l1 += v.y * w1; else h1 += v.y * w1;
        if (a2 < KLEN) l2 += v.z * w2; else h2 += v.z * w2;
        if (a3 < KLEN) l3 += v.w * w3; else h3 += v.w * w3;

        ++a0; ++a1; ++a2; ++a3;
        off += 4;
        if (++wn == 14) { wn = 0; off += 840; }   // next band
    }

    atomicAdd(&sAcc[R0    ], l0);
    atomicAdd(&sAcc[R0 + 1], h0);
    atomicAdd(&sAcc[R1    ], l1);
    atomicAdd(&sAcc[R1 + 1], h1);
    atomicAdd(&sAcc[R2    ], l2);
    atomicAdd(&sAcc[R2 + 1], h2);
    atomicAdd(&sAcc[R3    ], l3);
    atomicAdd(&sAcc[R3 + 1], h3);

    __syncthreads();

    if (tid < 98)
        out[(size_t)b * NROWS + ihalf * 98 + tid] = sAcc[tid] + bias[0];
}

extern "C" void kernel_launch(void* const* d_in, const int* in_sizes, int n_in,
                              void* d_out, int out_size)
{
    const float* x  = (const float*)d_in[0];   // (512,3,224,224)
    const float* W  = (const float*)d_in[1];   // (1,768)
    const float* bv = (const float*)d_in[2];   // (1,)
    float* out = (float*)d_out;                // (512,196)

    patch_scorer_kernel<<<BATCH * 2, TPB>>>(x, W, bv, out);
}